// round 1
// baseline (speedup 1.0000x reference)
#include <cuda_runtime.h>
#include <cuda_bf16.h>
#include <cstddef>

#define K_OFF   27
#define P_PAIRS 150000
#define CH      96
#define NOUT    600000
#define TILE    64
#define GTHREADS 192
#define A_STRIDE 100   // padded row stride (floats) for bank-conflict-free access

// ---------------- device globals (scratch; no allocation allowed) ----------
__device__ float  g_sum[CH];
__device__ float  g_sumsq[CH];
__device__ float4 g_scale4[CH / 4];
__device__ float4 g_bias4[CH / 4];

// ---------------- f32x2 packed-math helpers --------------------------------
__device__ __forceinline__ unsigned long long pack2(float lo, float hi) {
    unsigned long long r;
    asm("mov.b64 %0, {%1, %2};" : "=l"(r) : "f"(lo), "f"(hi));
    return r;
}
__device__ __forceinline__ void unpack2(unsigned long long v, float& lo, float& hi) {
    asm("mov.b64 {%0, %1}, %2;" : "=f"(lo), "=f"(hi) : "l"(v));
}
__device__ __forceinline__ unsigned long long ffma2(unsigned long long a,
                                                    unsigned long long b,
                                                    unsigned long long c) {
    unsigned long long d;
    asm("fma.rn.f32x2 %0, %1, %2, %3;" : "=l"(d) : "l"(a), "l"(b), "l"(c));
    return d;
}

// ---------------- GEMM + scatter kernel -------------------------------------
// grid: (ceil(P/64), 27), block: 192 threads
// smem: W[96][96] (9216 f) | A[64][100] (6400 f) | out_idx tile (64 i32)
__global__ void __launch_bounds__(GTHREADS, 2)
gemm_scatter_kernel(const float* __restrict__ feats,
                    const int*   __restrict__ in_idx,
                    const int*   __restrict__ out_idx,
                    const float* __restrict__ weight,
                    float*       __restrict__ out) {
    extern __shared__ float smem[];
    float* sW = smem;                 // 9216 floats
    float* sA = smem + 9216;          // 6400 floats (64 rows x 100 stride)
    int*   sO = (int*)(smem + 9216 + 6400); // 64 ints

    const int k    = blockIdx.y;
    const int base = blockIdx.x * TILE;
    const int tid  = threadIdx.x;

    // --- load W[k] (36 KB) cooperatively, vectorized ---
    {
        const float4* Wg = (const float4*)(weight + (size_t)k * (CH * CH));
        float4* sW4 = (float4*)sW;
        #pragma unroll
        for (int i = tid; i < (CH * CH) / 4; i += GTHREADS) sW4[i] = Wg[i];
    }

    // --- load output indices for this tile ---
    if (tid < TILE) {
        int p = base + tid;
        sO[tid] = (p < P_PAIRS) ? out_idx[(size_t)k * P_PAIRS + p] : 0;
    }

    // --- gather feature rows (64 rows x 24 float4) ---
    #pragma unroll
    for (int t = tid; t < TILE * 24; t += GTHREADS) {
        int row = t / 24;
        int q   = t % 24;
        int p   = base + row;
        float4 v = make_float4(0.f, 0.f, 0.f, 0.f);
        if (p < P_PAIRS) {
            int src = in_idx[(size_t)k * P_PAIRS + p];
            v = ((const float4*)(feats + (size_t)src * CH))[q];
        }
        *((float4*)(sA + row * A_STRIDE) + q) = v;
    }
    __syncthreads();

    // --- compute: thread (tx in [0,24), ty in [0,8)) owns rows {8i+ty}, cols tx*4..tx*4+3
    const int tx = tid % 24;
    const int ty = tid / 24;

    unsigned long long acc[8][2];
    #pragma unroll
    for (int i = 0; i < 8; i++) { acc[i][0] = 0ull; acc[i][1] = 0ull; }

    const float4* sW4 = (const float4*)sW;

    #pragma unroll 1
    for (int kk4 = 0; kk4 < CH / 4; kk4++) {
        unsigned long long bp[4][2];
        #pragma unroll
        for (int q = 0; q < 4; q++) {
            float4 bv = sW4[(kk4 * 4 + q) * 24 + tx];
            bp[q][0] = pack2(bv.x, bv.y);
            bp[q][1] = pack2(bv.z, bv.w);
        }
        #pragma unroll
        for (int i = 0; i < 8; i++) {
            const int r = i * 8 + ty;
            float4 av = *((const float4*)(sA + r * A_STRIDE) + kk4);
            unsigned long long ap;
            ap = pack2(av.x, av.x);
            acc[i][0] = ffma2(ap, bp[0][0], acc[i][0]);
            acc[i][1] = ffma2(ap, bp[0][1], acc[i][1]);
            ap = pack2(av.y, av.y);
            acc[i][0] = ffma2(ap, bp[1][0], acc[i][0]);
            acc[i][1] = ffma2(ap, bp[1][1], acc[i][1]);
            ap = pack2(av.z, av.z);
            acc[i][0] = ffma2(ap, bp[2][0], acc[i][0]);
            acc[i][1] = ffma2(ap, bp[2][1], acc[i][1]);
            ap = pack2(av.w, av.w);
            acc[i][0] = ffma2(ap, bp[3][0], acc[i][0]);
            acc[i][1] = ffma2(ap, bp[3][1], acc[i][1]);
        }
    }

    // --- scatter: 4 atomic adds per owned row ---
    #pragma unroll
    for (int i = 0; i < 8; i++) {
        const int r = i * 8 + ty;
        const int p = base + r;
        if (p < P_PAIRS) {
            float c0, c1, c2, c3;
            unpack2(acc[i][0], c0, c1);
            unpack2(acc[i][1], c2, c3);
            float* dst = out + (size_t)sO[r] * CH + tx * 4;
            atomicAdd(dst + 0, c0);
            atomicAdd(dst + 1, c1);
            atomicAdd(dst + 2, c2);
            atomicAdd(dst + 3, c3);
        }
    }
}

// ---------------- BN stat kernels -------------------------------------------
__global__ void zero_stats_kernel() {
    int c = threadIdx.x;
    if (c < CH) { g_sum[c] = 0.f; g_sumsq[c] = 0.f; }
}

// block: (96, 4). Each (c, s) strides over rows; one atomic per c per block.
__global__ void stats_kernel(const float* __restrict__ out, int nblocks) {
    const int c = threadIdx.x;
    const int s = threadIdx.y;
    float acc = 0.f, acc2 = 0.f;
    #pragma unroll 4
    for (int r = blockIdx.x * 4 + s; r < NOUT; r += nblocks * 4) {
        float v = out[(size_t)r * CH + c];
        acc  += v;
        acc2 += v * v;
    }
    __shared__ float sh[4][CH];
    __shared__ float sh2[4][CH];
    sh[s][c] = acc;
    sh2[s][c] = acc2;
    __syncthreads();
    if (s == 0) {
        float t  = sh[0][c]  + sh[1][c]  + sh[2][c]  + sh[3][c];
        float t2 = sh2[0][c] + sh2[1][c] + sh2[2][c] + sh2[3][c];
        atomicAdd(&g_sum[c], t);
        atomicAdd(&g_sumsq[c], t2);
    }
}

__global__ void finalize_kernel(const float* __restrict__ gamma,
                                const float* __restrict__ beta) {
    int c = threadIdx.x;
    if (c < CH) {
        const float invN = 1.0f / (float)NOUT;
        float mean = g_sum[c] * invN;
        float var  = g_sumsq[c] * invN - mean * mean;
        float sc   = gamma[c] * rsqrtf(var + 1e-5f);
        ((float*)g_scale4)[c] = sc;
        ((float*)g_bias4)[c]  = beta[c] - mean * sc;
    }
}

// ---------------- fused normalize + ReLU (in place) -------------------------
__global__ void norm_relu_kernel(float* __restrict__ out) {
    const long long NF4 = (long long)NOUT * (CH / 4);
    long long i      = (long long)blockIdx.x * blockDim.x + threadIdx.x;
    long long stride = (long long)gridDim.x * blockDim.x;
    float4* o4 = (float4*)out;
    for (; i < NF4; i += stride) {
        float4 v = o4[i];
        int c4 = (int)(i % (CH / 4));
        float4 s = g_scale4[c4];
        float4 b = g_bias4[c4];
        v.x = fmaxf(fmaf(v.x, s.x, b.x), 0.f);
        v.y = fmaxf(fmaf(v.y, s.y, b.y), 0.f);
        v.z = fmaxf(fmaf(v.z, s.z, b.z), 0.f);
        v.w = fmaxf(fmaf(v.w, s.w, b.w), 0.f);
        o4[i] = v;
    }
}

// ---------------- launch -----------------------------------------------------
extern "C" void kernel_launch(void* const* d_in, const int* in_sizes, int n_in,
                              void* d_out, int out_size) {
    const float* feats   = (const float*)d_in[0];
    const int*   in_idx  = (const int*)d_in[1];
    const int*   out_idx = (const int*)d_in[2];
    const float* weight  = (const float*)d_in[3];
    const float* gamma   = (const float*)d_in[4];
    const float* beta    = (const float*)d_in[5];
    float* out = (float*)d_out;

    const int smem_bytes = (9216 + 6400) * 4 + TILE * 4; // 62720
    cudaFuncSetAttribute(gemm_scatter_kernel,
                         cudaFuncAttributeMaxDynamicSharedMemorySize, smem_bytes);

    // zero accumulator (d_out is poisoned before timing)
    cudaMemsetAsync(d_out, 0, (size_t)NOUT * CH * sizeof(float), 0);
    zero_stats_kernel<<<1, CH>>>();

    dim3 grid((P_PAIRS + TILE - 1) / TILE, K_OFF);
    gemm_scatter_kernel<<<grid, GTHREADS, smem_bytes>>>(feats, in_idx, out_idx,
                                                        weight, out);

    const int STAT_BLOCKS = 1184;
    stats_kernel<<<STAT_BLOCKS, dim3(CH, 4)>>>(out, STAT_BLOCKS);
    finalize_kernel<<<1, CH>>>(gamma, beta);
    norm_relu_kernel<<<1184, 256>>>(out);
}